// round 1
// baseline (speedup 1.0000x reference)
#include <cuda_runtime.h>
#include <cuda_bf16.h>
#include <math.h>

// Problem constants (fixed by the reference setup)
#define B_SZ   16
#define T_SZ   3500
#define L_SZ   256
#define M_SZ   1024
#define NROWS  (B_SZ * T_SZ)          // 56000
#define ALPHA_F 10.0f
#define POW_EXP (-5.5f)               // -(ALPHA+1)/2

// Tiling
#define ROWS_PER_CTA 16               // 56000 / 16 = 3500 CTAs exactly
#define KC 8                          // K-chunk
#define KCP (KC + 1)                  // pad to 9 words: gcd(9,32)=1 -> conflict-free
#define THREADS 256

// Scratch for centroid squared norms (allocation-free per harness rules)
__device__ float g_b2[M_SZ];

// ---------------------------------------------------------------------------
// Kernel 1: b2[m] = sum_k centroids[m][k]^2   (1 MB read, trivial)
// ---------------------------------------------------------------------------
__global__ void som_b2_kernel(const float* __restrict__ cent) {
    int m = blockIdx.x * blockDim.x + threadIdx.x;
    if (m >= M_SZ) return;
    const float4* c4 = reinterpret_cast<const float4*>(cent) + (size_t)m * (L_SZ / 4);
    float s = 0.0f;
#pragma unroll 8
    for (int k = 0; k < L_SZ / 4; ++k) {
        float4 v = c4[k];
        s += v.x * v.x + v.y * v.y + v.z * v.z + v.w * v.w;
    }
    g_b2[m] = s;
}

// ---------------------------------------------------------------------------
// Kernel 2: fused  wz = z*tw ; d2 = |wz|^2 + |c|^2 - 2 wz.cT ; q = (1+d2/10)^-5.5
//           row-normalized over M, written once.
// One CTA = 16 rows x ALL 1024 columns (so normalization is in-register).
// Thread tile: 4 rows x 16 cols (cols strided by 64 for conflict-free smem).
// ---------------------------------------------------------------------------
__global__ void __launch_bounds__(THREADS, 2)
som_main_kernel(const float* __restrict__ z,
                const float* __restrict__ cent,
                const float* __restrict__ tw,
                float* __restrict__ out)
{
    __shared__ float cent_s[M_SZ * KCP];       // 36,864 B
    __shared__ float wz_s[ROWS_PER_CTA * KCP]; //    576 B
    __shared__ float b2_s[M_SZ];               //  4,096 B
    __shared__ float a2_s[ROWS_PER_CTA];
    __shared__ float tw_s[ROWS_PER_CTA];
    __shared__ float red[ROWS_PER_CTA][2];

    const int tid  = threadIdx.x;
    const int g    = tid >> 6;        // row-group 0..3  (4 rows each)
    const int c    = tid & 63;        // col-group 0..63 (cols c + 64*i)
    const int row0 = blockIdx.x * ROWS_PER_CTA;

    // ---- stage b2 into smem ----
#pragma unroll
    for (int i = tid; i < M_SZ; i += THREADS) b2_s[i] = g_b2[i];

    // ---- pre-pass: per-row time weight + a2 = tw^2 * sum(z^2) ----
    {
        const int ty = tid >> 4;          // row 0..15
        const int tx = tid & 15;          // 16-elem segment
        const int grow = row0 + ty;
        const int t = grow % T_SZ;
        const float twv = tw[t];
        if (tx == 0) tw_s[ty] = twv;
        const float* zr = z + (size_t)grow * L_SZ + tx * 16;
        float s = 0.0f;
#pragma unroll
        for (int k = 0; k < 16; ++k) { float v = zr[k]; s += v * v; }
        s *= twv * twv;
#pragma unroll
        for (int off = 8; off > 0; off >>= 1)
            s += __shfl_down_sync(0xffffffffu, s, off, 16);
        if (tx == 0) a2_s[ty] = s;
    }

    float acc[4][16];
#pragma unroll
    for (int j = 0; j < 4; ++j)
#pragma unroll
        for (int i = 0; i < 16; ++i) acc[j][i] = 0.0f;

    const float4* c4 = reinterpret_cast<const float4*>(cent);

    // ---- main K loop ----
    for (int k0 = 0; k0 < L_SZ; k0 += KC) {
        __syncthreads();
        // load centroid chunk: cent_s[m][0..7] = cent[m][k0..k0+7]
#pragma unroll
        for (int i = tid; i < M_SZ * (KC / 4); i += THREADS) {
            int m = i >> 1, h = i & 1;
            float4 v = c4[(size_t)m * (L_SZ / 4) + (k0 >> 2) + h];
            float* dst = &cent_s[m * KCP + h * 4];
            dst[0] = v.x; dst[1] = v.y; dst[2] = v.z; dst[3] = v.w;
        }
        // load wz chunk
        if (tid < ROWS_PER_CTA * KC) {
            int r = tid >> 3, kk = tid & 7;
            wz_s[r * KCP + kk] =
                z[(size_t)(row0 + r) * L_SZ + k0 + kk] * tw_s[r];
        }
        __syncthreads();

#pragma unroll
        for (int k = 0; k < KC; ++k) {
            float cv[16];
#pragma unroll
            for (int i = 0; i < 16; ++i)
                cv[i] = cent_s[(c + (i << 6)) * KCP + k];
            float wv[4];
#pragma unroll
            for (int j = 0; j < 4; ++j)
                wv[j] = wz_s[((g << 2) + j) * KCP + k];
#pragma unroll
            for (int j = 0; j < 4; ++j)
#pragma unroll
                for (int i = 0; i < 16; ++i)
                    acc[j][i] = fmaf(wv[j], cv[i], acc[j][i]);
        }
    }
    __syncthreads();

    // ---- epilogue: q = (1 + d2/alpha)^-5.5, row-normalize, store ----
    float rs[4] = {0.f, 0.f, 0.f, 0.f};
#pragma unroll
    for (int j = 0; j < 4; ++j) {
        const float a2v = a2_s[(g << 2) + j];
#pragma unroll
        for (int i = 0; i < 16; ++i) {
            const int m = c + (i << 6);
            float d2 = a2v + b2_s[m] - 2.0f * acc[j][i];
            d2 = fmaxf(d2, 0.0f);
            float qv = __powf(fmaf(d2, 1.0f / ALPHA_F, 1.0f), POW_EXP);
            acc[j][i] = qv;
            rs[j] += qv;
        }
    }

    // reduce row sums over the 64 threads (2 warps) sharing each row
    const int halfwarp = (tid >> 5) & 1;   // which warp within the row-group
#pragma unroll
    for (int j = 0; j < 4; ++j) {
        float v = rs[j];
#pragma unroll
        for (int off = 16; off > 0; off >>= 1)
            v += __shfl_down_sync(0xffffffffu, v, off);
        if ((tid & 31) == 0) red[(g << 2) + j][halfwarp] = v;
    }
    __syncthreads();

    float inv[4];
#pragma unroll
    for (int j = 0; j < 4; ++j) {
        float s = red[(g << 2) + j][0] + red[(g << 2) + j][1];
        inv[j] = 1.0f / (s + 1e-8f);
    }

#pragma unroll
    for (int j = 0; j < 4; ++j) {
        const size_t rbase = (size_t)(row0 + (g << 2) + j) * M_SZ;
#pragma unroll
        for (int i = 0; i < 16; ++i)
            out[rbase + c + (i << 6)] = acc[j][i] * inv[j];
    }
}

// ---------------------------------------------------------------------------
extern "C" void kernel_launch(void* const* d_in, const int* in_sizes, int n_in,
                              void* d_out, int out_size)
{
    const float* z    = (const float*)d_in[0];   // (16, 3500, 256)
    const float* cent = (const float*)d_in[1];   // (1024, 256)
    const float* tw   = (const float*)d_in[2];   // (1, 3500, 1)
    float* out = (float*)d_out;                  // (16, 3500, 1024)

    som_b2_kernel<<<(M_SZ + 255) / 256, 256>>>(cent);
    som_main_kernel<<<NROWS / ROWS_PER_CTA, THREADS>>>(z, cent, tw, out);
}

// round 3
// speedup vs baseline: 3.5780x; 3.5780x over previous
#include <cuda_runtime.h>
#include <cuda_bf16.h>
#include <cstdint>

// ---------------- problem constants ----------------
#define T_SZ   3500
#define L_SZ   256
#define M_SZ   1024
#define NROWS  56000
#define ROWS_CTA 128
#define NCTA   ((NROWS + ROWS_CTA - 1) / ROWS_CTA)   // 438

// ---------------- SMEM layout (bytes, dynamic) ----------------
#define SM_AHI 0          // 128 x 256 bf16 (swizzled)        64KB
#define SM_ALO 65536      // 64KB
#define SM_B   131072     // 2 bufs x (hi 16KB + lo 16KB)     64KB
#define SM_B2  196608     // 1024 floats                       4KB
#define SM_A2  200704     // 128 floats                       512B
#define SM_RS  201216     // 128 floats                       512B
#define SMEM_TOTAL 201728

// ---------------- device globals (allocation-free scratch) ----------------
__device__ __nv_bfloat16 g_chi[M_SZ * L_SZ];
__device__ __nv_bfloat16 g_clo[M_SZ * L_SZ];
__device__ float g_b2[M_SZ];
__device__ float g_inv[NROWS];

// ---------------- PTX helpers (baseline ISA only: sm_80+) ----------------
__device__ __forceinline__ uint32_t smem_to_u32(const void* p) {
    uint32_t a;
    asm("{ .reg .u64 t; cvta.to.shared.u64 t, %1; cvt.u32.u64 %0, t; }"
        : "=r"(a) : "l"(p));
    return a;
}

__device__ __forceinline__ void ldsm4(uint32_t* r, uint32_t addr) {
    asm volatile("ldmatrix.sync.aligned.m8n8.x4.shared.b16 {%0,%1,%2,%3}, [%4];"
        : "=r"(r[0]), "=r"(r[1]), "=r"(r[2]), "=r"(r[3]) : "r"(addr));
}

__device__ __forceinline__ void mma16816(float* d, const uint32_t* a, const uint32_t* b) {
    asm volatile(
        "mma.sync.aligned.m16n8k16.row.col.f32.bf16.bf16.f32 "
        "{%0,%1,%2,%3}, {%4,%5,%6,%7}, {%8,%9}, {%0,%1,%2,%3};"
        : "+f"(d[0]), "+f"(d[1]), "+f"(d[2]), "+f"(d[3])
        : "r"(a[0]), "r"(a[1]), "r"(a[2]), "r"(a[3]), "r"(b[0]), "r"(b[1]));
}

#define CP_ASYNC16(dst, src) \
    asm volatile("cp.async.cg.shared.global [%0], [%1], 16;" :: "r"(dst), "l"(src))
#define CP_COMMIT asm volatile("cp.async.commit_group;" ::: "memory")
#define CP_WAIT1  asm volatile("cp.async.wait_group 1;" ::: "memory")

// ---------------------------------------------------------------------------
// Kernel 1 (prep): centroids -> bf16 hi/lo split + b2 norms
// ---------------------------------------------------------------------------
__global__ void som_prep_kernel(const float* __restrict__ cent) {
    int m = blockIdx.x;
    int lane = threadIdx.x;   // 32 threads
    const float4* c4 = reinterpret_cast<const float4*>(cent + (size_t)m * L_SZ);
    float s = 0.f;
#pragma unroll
    for (int i = 0; i < 2; ++i) {
        float4 v = c4[lane * 2 + i];
        float vv[4] = {v.x, v.y, v.z, v.w};
#pragma unroll
        for (int j = 0; j < 4; ++j) {
            float x = vv[j];
            s += x * x;
            __nv_bfloat16 h = __float2bfloat16(x);
            float r = x - __bfloat162float(h);
            int k = lane * 8 + i * 4 + j;
            g_chi[(size_t)m * L_SZ + k] = h;
            g_clo[(size_t)m * L_SZ + k] = __float2bfloat16(r);
        }
    }
#pragma unroll
    for (int o = 16; o > 0; o >>= 1) s += __shfl_down_sync(0xffffffffu, s, o);
    if (lane == 0) g_b2[m] = s;
}

// ---------------------------------------------------------------------------
// Kernel 2 (main): bf16x3 GEMM via mma.sync + fused epilogue.
// CTA = 128 rows x full 1024 cols (8 chunks of 128). 8 warps, warp tile 32x64.
// ---------------------------------------------------------------------------
__global__ void __launch_bounds__(256, 1)
som_mma_kernel(const float* __restrict__ z,
               const float* __restrict__ tw,
               float* __restrict__ out)
{
    extern __shared__ char smem[];
    const uint32_t sb = smem_to_u32(smem);
    const int tid  = threadIdx.x;
    const int wid  = tid >> 5;
    const int l    = tid & 31;
    const int wr   = wid >> 1;        // warp row 0..3  (32 rows each)
    const int wc   = wid & 1;         // warp col 0..1  (64 cols each)
    const int row0 = blockIdx.x * ROWS_CTA;

    float* b2s = (float*)(smem + SM_B2);
    float* a2s = (float*)(smem + SM_A2);
    float* rss = (float*)(smem + SM_RS);

    for (int i = tid; i < M_SZ; i += 256) b2s[i] = g_b2[i];
    if (tid < 128) rss[tid] = 0.f;

    // ---- A prologue: wz = z*tw -> bf16 hi/lo, swizzled smem; a2 = |wz|^2 ----
    {
        const int r = tid >> 1;            // row 0..127
        const int seg = tid & 1;           // which 128-k half
        const int grow = row0 + r;
        const bool ok = (grow < NROWS);
        const float twv = ok ? tw[grow % T_SZ] : 0.f;
        float s = 0.f;
        const float4* zr = reinterpret_cast<const float4*>(z + (size_t)grow * L_SZ) + seg * 32;
#pragma unroll
        for (int p = 0; p < 16; ++p) {
            float w[8];
            if (ok) {
                float4 v0 = zr[p * 2], v1 = zr[p * 2 + 1];
                w[0]=v0.x*twv; w[1]=v0.y*twv; w[2]=v0.z*twv; w[3]=v0.w*twv;
                w[4]=v1.x*twv; w[5]=v1.y*twv; w[6]=v1.z*twv; w[7]=v1.w*twv;
            } else {
#pragma unroll
                for (int j = 0; j < 8; ++j) w[j] = 0.f;
            }
            uint32_t hi[4], lo[4];
#pragma unroll
            for (int j = 0; j < 4; ++j) {
                float a = w[2*j], b = w[2*j+1];
                s += a * a + b * b;
                __nv_bfloat16 ha = __float2bfloat16(a), hb = __float2bfloat16(b);
                float ra = a - __bfloat162float(ha), rb = b - __bfloat162float(hb);
                __nv_bfloat16 la = __float2bfloat16(ra), lb = __float2bfloat16(rb);
                hi[j] = ((uint32_t)__bfloat16_as_ushort(hb) << 16) | __bfloat16_as_ushort(ha);
                lo[j] = ((uint32_t)__bfloat16_as_ushort(lb) << 16) | __bfloat16_as_ushort(la);
            }
            const int kc = seg * 16 + p;                       // 8-elem chunk id 0..31
            const uint32_t off = r * 512 + ((kc ^ (r & 7)) << 4);
            *(uint4*)(smem + SM_AHI + off) = make_uint4(hi[0], hi[1], hi[2], hi[3]);
            *(uint4*)(smem + SM_ALO + off) = make_uint4(lo[0], lo[1], lo[2], lo[3]);
        }
        s += __shfl_xor_sync(0xffffffffu, s, 1);
        if (seg == 0) a2s[r] = s;
    }
    __syncthreads();

    // ---- lane-constant address pieces ----
    const int swz = l & 7;                         // swizzle xor (rows/cols mult of 16)
    uint32_t aRow[2];                              // A row byte offset per m-frag
#pragma unroll
    for (int mf = 0; mf < 2; ++mf)
        aRow[mf] = (uint32_t)(wr * 32 + mf * 16 + (l & 15)) * 512;
    const int aKpart = (l >> 4);                   // +1 k-chunk for lanes 16-31
    uint32_t bRow[4];                              // B row byte offset per n-pair
#pragma unroll
    for (int p = 0; p < 4; ++p)
        bRow[p] = (uint32_t)(wc * 64 + p * 16 + (l & 7) + ((l & 16) >> 1)) * 128;
    const int bKpart = (l >> 3) & 1;

    float acc[2][8][4];
#pragma unroll
    for (int mf = 0; mf < 2; ++mf)
#pragma unroll
        for (int nf = 0; nf < 8; ++nf)
#pragma unroll
            for (int e = 0; e < 4; ++e) acc[mf][nf][e] = 0.f;

    // ---- B cp.async loader (step = nc*4 + kcb; 64-k chunk per step) ----
    auto load_step = [&](int s) {
        const int nc = s >> 2, kcb = s & 3;
        const uint32_t bufHi = sb + SM_B + (uint32_t)(s & 1) * 32768u;
        const uint32_t bufLo = bufHi + 16384u;
#pragma unroll
        for (int i = 0; i < 4; ++i) {
            const int c = tid * 4 + i;             // chunk 0..1023
            const int n = c >> 3, k8 = c & 7;
            const size_t src = ((size_t)(nc * 128 + n) * 256 + kcb * 64 + k8 * 8);
            const uint32_t doff = (uint32_t)n * 128 + (uint32_t)((k8 ^ (n & 7)) << 4);
            CP_ASYNC16(bufHi + doff, (const char*)g_chi + src * 2);
            CP_ASYNC16(bufLo + doff, (const char*)g_clo + src * 2);
        }
    };

    load_step(0);
    CP_COMMIT;

    for (int s = 0; s < 32; ++s) {
        const int nc = s >> 2, kcb = s & 3;
        if (s + 1 < 32) load_step(s + 1);
        CP_COMMIT;
        CP_WAIT1;
        __syncthreads();

        const uint32_t bufHi = sb + SM_B + (uint32_t)(s & 1) * 32768u;
        const uint32_t bufLo = bufHi + 16384u;
        const uint32_t aHi = sb + SM_AHI, aLo = sb + SM_ALO;

#pragma unroll
        for (int k16 = 0; k16 < 4; ++k16) {
            const int kcA = kcb * 8 + k16 * 2 + aKpart;        // chunk in 0..31
            const int kcB = k16 * 2 + bKpart;                  // chunk in 0..7
            uint32_t ah[2][4], al[2][4], bh[4][4], bl[4][4];
#pragma unroll
            for (int mf = 0; mf < 2; ++mf) {
                const uint32_t ao = aRow[mf] + ((kcA ^ swz) << 4);
                ldsm4(ah[mf], aHi + ao);
                ldsm4(al[mf], aLo + ao);
            }
#pragma unroll
            for (int p = 0; p < 4; ++p) {
                const uint32_t bo = bRow[p] + ((kcB ^ swz) << 4);
                ldsm4(bh[p], bufHi + bo);
                ldsm4(bl[p], bufLo + bo);
            }
#pragma unroll
            for (int mf = 0; mf < 2; ++mf)
#pragma unroll
                for (int nf = 0; nf < 8; ++nf) {
                    const int p = nf >> 1, h = (nf & 1) * 2;
                    mma16816(acc[mf][nf], ah[mf], &bh[p][h]);
                    mma16816(acc[mf][nf], ah[mf], &bl[p][h]);
                    mma16816(acc[mf][nf], al[mf], &bh[p][h]);
                }
        }

        // ---- epilogue once per col-chunk ----
        if (kcb == 3) {
#pragma unroll
            for (int mf = 0; mf < 2; ++mf)
#pragma unroll
                for (int rh = 0; rh < 2; ++rh) {
                    const int row = wr * 32 + mf * 16 + rh * 8 + (l >> 2);
                    const int grow = row0 + row;
                    const float a2v = a2s[row];
                    float rsum = 0.f;
                    float2 st[8];
#pragma unroll
                    for (int nf = 0; nf < 8; ++nf) {
                        const int mcol = nc * 128 + wc * 64 + nf * 8 + (l & 3) * 2;
                        float d0 = a2v + b2s[mcol]     - 2.f * acc[mf][nf][rh * 2];
                        float d1 = a2v + b2s[mcol + 1] - 2.f * acc[mf][nf][rh * 2 + 1];
                        d0 = fmaxf(d0, 0.f); d1 = fmaxf(d1, 0.f);
                        float q0 = __powf(fmaf(d0, 0.1f, 1.f), -5.5f);
                        float q1 = __powf(fmaf(d1, 0.1f, 1.f), -5.5f);
                        rsum += q0 + q1;
                        st[nf] = make_float2(q0, q1);
                        acc[mf][nf][rh * 2] = 0.f;
                        acc[mf][nf][rh * 2 + 1] = 0.f;
                    }
                    float v = rsum;
                    v += __shfl_xor_sync(0xffffffffu, v, 1);
                    v += __shfl_xor_sync(0xffffffffu, v, 2);
                    if ((l & 3) == 0) atomicAdd(&rss[row], v);
                    if (grow < NROWS) {
                        float* orow = out + (size_t)grow * M_SZ + nc * 128 + wc * 64;
#pragma unroll
                        for (int nf = 0; nf < 8; ++nf)
                            *(float2*)(orow + nf * 8 + (l & 3) * 2) = st[nf];
                    }
                }
        }
        __syncthreads();
    }

    if (tid < 128 && row0 + tid < NROWS)
        g_inv[row0 + tid] = 1.f / (rss[tid] + 1e-8f);
}

// ---------------------------------------------------------------------------
// Kernel 3: normalize in place   out[r, :] *= g_inv[r]
// ---------------------------------------------------------------------------
__global__ void som_scale_kernel(float* __restrict__ out) {
    float4* o4 = reinterpret_cast<float4*>(out);
    const int base = blockIdx.x * 1024 + threadIdx.x;
#pragma unroll
    for (int k = 0; k < 4; ++k) {
        const int f = base + k * 256;          // float4 index
        const float inv = g_inv[f >> 8];
        float4 v = o4[f];
        v.x *= inv; v.y *= inv; v.z *= inv; v.w *= inv;
        o4[f] = v;
    }
}

// ---------------------------------------------------------------------------
extern "C" void kernel_launch(void* const* d_in, const int* in_sizes, int n_in,
                              void* d_out, int out_size)
{
    const float* z    = (const float*)d_in[0];   // (16, 3500, 256)
    const float* cent = (const float*)d_in[1];   // (1024, 256)
    const float* tw   = (const float*)d_in[2];   // (3500)
    float* out = (float*)d_out;                  // (16, 3500, 1024)

    cudaFuncSetAttribute(som_mma_kernel,
                         cudaFuncAttributeMaxDynamicSharedMemorySize, SMEM_TOTAL);

    som_prep_kernel<<<M_SZ, 32>>>(cent);
    som_mma_kernel<<<NCTA, 256, SMEM_TOTAL>>>(z, tw, out);
    som_scale_kernel<<<14000, 256>>>(out);
}

// round 4
// speedup vs baseline: 4.0250x; 1.1249x over previous
#include <cuda_runtime.h>
#include <cuda_bf16.h>
#include <cstdint>

// ---------------- problem constants ----------------
#define T_SZ   3500
#define L_SZ   256
#define M_SZ   1024
#define NROWS  56000
#define ROWS_CTA 128
#define NCTA   ((NROWS + ROWS_CTA - 1) / ROWS_CTA)   // 438
#define NTHREADS 512

// ---------------- SMEM layout (bytes, dynamic) ----------------
#define SM_AHI 0          // 128 x 256 bf16 (swizzled)        64KB
#define SM_ALO 65536      // 64KB
#define SM_B   131072     // 2 bufs x (hi 16KB + lo 16KB)     64KB
#define SM_B2  196608     // 1024 floats                       4KB
#define SM_A2  200704     // 128 floats                       512B
#define SM_RS  201216     // 128 floats                       512B
#define SMEM_TOTAL 201728

// ---------------- device globals (allocation-free scratch) ----------------
__device__ __nv_bfloat16 g_chi[M_SZ * L_SZ];
__device__ __nv_bfloat16 g_clo[M_SZ * L_SZ];
__device__ float g_b2[M_SZ];

// ---------------- PTX helpers (baseline ISA only: sm_80+) ----------------
__device__ __forceinline__ uint32_t smem_to_u32(const void* p) {
    uint32_t a;
    asm("{ .reg .u64 t; cvta.to.shared.u64 t, %1; cvt.u32.u64 %0, t; }"
        : "=r"(a) : "l"(p));
    return a;
}

__device__ __forceinline__ void ldsm4(uint32_t* r, uint32_t addr) {
    asm volatile("ldmatrix.sync.aligned.m8n8.x4.shared.b16 {%0,%1,%2,%3}, [%4];"
        : "=r"(r[0]), "=r"(r[1]), "=r"(r[2]), "=r"(r[3]) : "r"(addr));
}

__device__ __forceinline__ void mma16816(float* d, const uint32_t* a, const uint32_t* b) {
    asm volatile(
        "mma.sync.aligned.m16n8k16.row.col.f32.bf16.bf16.f32 "
        "{%0,%1,%2,%3}, {%4,%5,%6,%7}, {%8,%9}, {%0,%1,%2,%3};"
        : "+f"(d[0]), "+f"(d[1]), "+f"(d[2]), "+f"(d[3])
        : "r"(a[0]), "r"(a[1]), "r"(a[2]), "r"(a[3]), "r"(b[0]), "r"(b[1]));
}

#define CP_ASYNC16(dst, src) \
    asm volatile("cp.async.cg.shared.global [%0], [%1], 16;" :: "r"(dst), "l"(src))
#define CP_COMMIT asm volatile("cp.async.commit_group;" ::: "memory")
#define CP_WAIT1  asm volatile("cp.async.wait_group 1;" ::: "memory")

// ---------------------------------------------------------------------------
// Kernel 1 (prep): centroids -> bf16 hi/lo split + b2 norms (1 warp per row)
// ---------------------------------------------------------------------------
__global__ void som_prep_kernel(const float* __restrict__ cent) {
    int m = blockIdx.x * 8 + (threadIdx.x >> 5);
    int lane = threadIdx.x & 31;
    const float4* c4 = reinterpret_cast<const float4*>(cent + (size_t)m * L_SZ);
    float s = 0.f;
#pragma unroll
    for (int i = 0; i < 2; ++i) {
        float4 v = c4[lane * 2 + i];
        float vv[4] = {v.x, v.y, v.z, v.w};
#pragma unroll
        for (int j = 0; j < 4; ++j) {
            float x = vv[j];
            s += x * x;
            __nv_bfloat16 h = __float2bfloat16(x);
            float r = x - __bfloat162float(h);
            int k = lane * 8 + i * 4 + j;
            g_chi[(size_t)m * L_SZ + k] = h;
            g_clo[(size_t)m * L_SZ + k] = __float2bfloat16(r);
        }
    }
#pragma unroll
    for (int o = 16; o > 0; o >>= 1) s += __shfl_down_sync(0xffffffffu, s, o);
    if (lane == 0) g_b2[m] = s;
}

// ---------------------------------------------------------------------------
// Kernel 2 (main): bf16x3 GEMM via mma.sync + fused epilogue + fused normalize.
// CTA = 128 rows x full 1024 cols (8 chunks of 128).
// 16 warps, warp grid 8x2, warp tile 16 rows x 64 cols.
// ---------------------------------------------------------------------------
__global__ void __launch_bounds__(NTHREADS, 1)
som_mma_kernel(const float* __restrict__ z,
               const float* __restrict__ tw,
               float* __restrict__ out)
{
    extern __shared__ char smem[];
    const uint32_t sb = smem_to_u32(smem);
    const int tid  = threadIdx.x;
    const int wid  = tid >> 5;
    const int l    = tid & 31;
    const int wr   = wid >> 1;        // warp row 0..7  (16 rows each)
    const int wc   = wid & 1;         // warp col 0..1  (64 cols each)
    const int row0 = blockIdx.x * ROWS_CTA;

    float* b2s = (float*)(smem + SM_B2);
    float* a2s = (float*)(smem + SM_A2);
    float* rss = (float*)(smem + SM_RS);

    for (int i = tid; i < M_SZ; i += NTHREADS) b2s[i] = g_b2[i];
    if (tid < 128) rss[tid] = 0.f;

    // ---- A prologue: wz = z*tw -> bf16 hi/lo, swizzled smem; a2 = |wz|^2 ----
    {
        const int r = tid >> 2;            // row 0..127
        const int seg = tid & 3;           // 64-k quarter
        const int grow = row0 + r;
        const bool ok = (grow < NROWS);
        const float twv = ok ? tw[grow % T_SZ] : 0.f;
        float s = 0.f;
        const float4* zr = reinterpret_cast<const float4*>(z + (size_t)grow * L_SZ) + seg * 16;
#pragma unroll
        for (int p = 0; p < 8; ++p) {
            float w[8];
            if (ok) {
                float4 v0 = zr[p * 2], v1 = zr[p * 2 + 1];
                w[0]=v0.x*twv; w[1]=v0.y*twv; w[2]=v0.z*twv; w[3]=v0.w*twv;
                w[4]=v1.x*twv; w[5]=v1.y*twv; w[6]=v1.z*twv; w[7]=v1.w*twv;
            } else {
#pragma unroll
                for (int j = 0; j < 8; ++j) w[j] = 0.f;
            }
            uint32_t hi[4], lo[4];
#pragma unroll
            for (int j = 0; j < 4; ++j) {
                float a = w[2*j], b = w[2*j+1];
                s += a * a + b * b;
                __nv_bfloat16 ha = __float2bfloat16(a), hb = __float2bfloat16(b);
                float ra = a - __bfloat162float(ha), rb = b - __bfloat162float(hb);
                __nv_bfloat16 la = __float2bfloat16(ra), lb = __float2bfloat16(rb);
                hi[j] = ((uint32_t)__bfloat16_as_ushort(hb) << 16) | __bfloat16_as_ushort(ha);
                lo[j] = ((uint32_t)__bfloat16_as_ushort(lb) << 16) | __bfloat16_as_ushort(la);
            }
            const int kc = seg * 8 + p;                        // 8-elem chunk id 0..31
            const uint32_t off = r * 512 + ((kc ^ (r & 7)) << 4);
            *(uint4*)(smem + SM_AHI + off) = make_uint4(hi[0], hi[1], hi[2], hi[3]);
            *(uint4*)(smem + SM_ALO + off) = make_uint4(lo[0], lo[1], lo[2], lo[3]);
        }
        s += __shfl_xor_sync(0xffffffffu, s, 1);
        s += __shfl_xor_sync(0xffffffffu, s, 2);
        if (seg == 0) a2s[r] = s;
    }
    __syncthreads();

    // ---- lane-constant address pieces ----
    const int swz = l & 7;
    const uint32_t aRow = (uint32_t)(wr * 16 + (l & 15)) * 512;
    const int aKpart = (l >> 4);                   // +1 k-chunk for lanes 16-31
    uint32_t bRow[4];
#pragma unroll
    for (int p = 0; p < 4; ++p)
        bRow[p] = (uint32_t)(wc * 64 + p * 16 + (l & 7) + ((l & 16) >> 1)) * 128;
    const int bKpart = (l >> 3) & 1;

    float acc[8][4];
#pragma unroll
    for (int nf = 0; nf < 8; ++nf)
#pragma unroll
        for (int e = 0; e < 4; ++e) acc[nf][e] = 0.f;

    // ---- B cp.async loader (step = nc*4 + kcb; 64-k chunk per step) ----
    auto load_step = [&](int s) {
        const int nc = s >> 2, kcb = s & 3;
        const uint32_t bufHi = sb + SM_B + (uint32_t)(s & 1) * 32768u;
        const uint32_t bufLo = bufHi + 16384u;
#pragma unroll
        for (int i = 0; i < 2; ++i) {
            const int c = tid * 2 + i;             // chunk 0..1023
            const int n = c >> 3, k8 = c & 7;
            const size_t src = ((size_t)(nc * 128 + n) * 256 + kcb * 64 + k8 * 8);
            const uint32_t doff = (uint32_t)n * 128 + (uint32_t)((k8 ^ (n & 7)) << 4);
            CP_ASYNC16(bufHi + doff, (const char*)g_chi + src * 2);
            CP_ASYNC16(bufLo + doff, (const char*)g_clo + src * 2);
        }
    };

    load_step(0);
    CP_COMMIT;

    for (int s = 0; s < 32; ++s) {
        const int nc = s >> 2, kcb = s & 3;
        if (s + 1 < 32) load_step(s + 1);
        CP_COMMIT;
        CP_WAIT1;
        __syncthreads();

        const uint32_t bufHi = sb + SM_B + (uint32_t)(s & 1) * 32768u;
        const uint32_t bufLo = bufHi + 16384u;
        const uint32_t aHi = sb + SM_AHI, aLo = sb + SM_ALO;

#pragma unroll
        for (int k16 = 0; k16 < 4; ++k16) {
            const int kcA = kcb * 8 + k16 * 2 + aKpart;        // chunk in 0..31
            const int kcB = k16 * 2 + bKpart;                  // chunk in 0..7
            uint32_t ah[4], al[4], bh[4][4], bl[4][4];
            {
                const uint32_t ao = aRow + ((kcA ^ swz) << 4);
                ldsm4(ah, aHi + ao);
                ldsm4(al, aLo + ao);
            }
#pragma unroll
            for (int p = 0; p < 4; ++p) {
                const uint32_t bo = bRow[p] + ((kcB ^ swz) << 4);
                ldsm4(bh[p], bufHi + bo);
                ldsm4(bl[p], bufLo + bo);
            }
#pragma unroll
            for (int nf = 0; nf < 8; ++nf) {
                const int p = nf >> 1, h = (nf & 1) * 2;
                mma16816(acc[nf], ah, &bh[p][h]);
                mma16816(acc[nf], ah, &bl[p][h]);
                mma16816(acc[nf], al, &bh[p][h]);
            }
        }

        // ---- epilogue once per col-chunk ----
        if (kcb == 3) {
#pragma unroll
            for (int rh = 0; rh < 2; ++rh) {
                const int row = wr * 16 + rh * 8 + (l >> 2);
                const int grow = row0 + row;
                const float a2v = a2s[row];
                float rsum = 0.f;
                float2 st[8];
#pragma unroll
                for (int nf = 0; nf < 8; ++nf) {
                    const int mcol = nc * 128 + wc * 64 + nf * 8 + (l & 3) * 2;
                    float d0 = a2v + b2s[mcol]     - 2.f * acc[nf][rh * 2];
                    float d1 = a2v + b2s[mcol + 1] - 2.f * acc[nf][rh * 2 + 1];
                    d0 = fmaxf(d0, 0.f); d1 = fmaxf(d1, 0.f);
                    float q0 = __powf(fmaf(d0, 0.1f, 1.f), -5.5f);
                    float q1 = __powf(fmaf(d1, 0.1f, 1.f), -5.5f);
                    rsum += q0 + q1;
                    st[nf] = make_float2(q0, q1);
                    acc[nf][rh * 2] = 0.f;
                    acc[nf][rh * 2 + 1] = 0.f;
                }
                float v = rsum;
                v += __shfl_xor_sync(0xffffffffu, v, 1);
                v += __shfl_xor_sync(0xffffffffu, v, 2);
                if ((l & 3) == 0) atomicAdd(&rss[row], v);
                if (grow < NROWS) {
                    float* orow = out + (size_t)grow * M_SZ + nc * 128 + wc * 64;
#pragma unroll
                    for (int nf = 0; nf < 8; ++nf)
                        *(float2*)(orow + nf * 8 + (l & 3) * 2) = st[nf];
                }
            }
        }
        __syncthreads();
    }

    // ---- fused normalization: re-read tile (L2-resident), scale, rewrite ----
    if (tid < 128) rss[tid] = 1.f / (rss[tid] + 1e-8f);
    __syncthreads();
    {
        // 128 rows x 1024 cols = 32768 float4 (256 float4 per row)
        const int nrow = (row0 + ROWS_CTA <= NROWS) ? ROWS_CTA : (NROWS - row0);
        for (int i = tid; i < nrow * 256; i += NTHREADS) {
            const int r_ = i >> 8;
            const float inv = rss[r_];
            float4* p4 = reinterpret_cast<float4*>(out + (size_t)(row0 + r_) * M_SZ) + (i & 255);
            float4 v = *p4;
            v.x *= inv; v.y *= inv; v.z *= inv; v.w *= inv;
            *p4 = v;
        }
    }
}

// ---------------------------------------------------------------------------
extern "C" void kernel_launch(void* const* d_in, const int* in_sizes, int n_in,
                              void* d_out, int out_size)
{
    const float* z    = (const float*)d_in[0];   // (16, 3500, 256)
    const float* cent = (const float*)d_in[1];   // (1024, 256)
    const float* tw   = (const float*)d_in[2];   // (3500)
    float* out = (float*)d_out;                  // (16, 3500, 1024)

    cudaFuncSetAttribute(som_mma_kernel,
                         cudaFuncAttributeMaxDynamicSharedMemorySize, SMEM_TOTAL);

    som_prep_kernel<<<M_SZ / 8, 256>>>(cent);
    som_mma_kernel<<<NCTA, NTHREADS, SMEM_TOTAL>>>(z, tw, out);
}